// round 16
// baseline (speedup 1.0000x reference)
#include <cuda_runtime.h>
#include <cuda.h>
#include <cuda_bf16.h>
#include <cstdint>
#include <math.h>

#define B_ 4
#define T_ 2048
#define C_ 2048
#define NH_ 2048
#define KH_ 512
#define QKV_ 3072      // NH_ + KH_ + KH_
#define NHEADS 16
#define H_ 128
#define M_ (B_*T_)

typedef __nv_bfloat16 bf16;

#if defined(__CUDA_ARCH_FEAT_SM103_ALL) || defined(__CUDA_ARCH_FEAT_SM100_ALL)
#define HAS_TCGEN05 1
#else
#define HAS_TCGEN05 0
#endif

// ---------------------------------------------------------------------------
// Device-global scratch
// ---------------------------------------------------------------------------
__device__ float g_qkv[(size_t)M_ * QKV_];

__device__ bf16 g_x_hi[(size_t)M_ * C_],  g_x_lo[(size_t)M_ * C_];
__device__ bf16 g_e_hi[(size_t)M_ * NH_], g_e_lo[(size_t)M_ * NH_];
__device__ bf16 g_qh[(size_t)M_ * NH_],   g_ql[(size_t)M_ * NH_];
__device__ bf16 g_kh[(size_t)M_ * KH_],   g_kl[(size_t)M_ * KH_];
__device__ bf16 g_vth[(size_t)16 * 128 * T_], g_vtl[(size_t)16 * 128 * T_];
__device__ bf16 g_Wc_hi[(size_t)QKV_ * C_], g_Wc_lo[(size_t)QKV_ * C_];
__device__ bf16 g_Wo_hi[(size_t)C_ * NH_],  g_Wo_lo[(size_t)C_ * NH_];

// ---------------------------------------------------------------------------
// PTX helpers
// ---------------------------------------------------------------------------
__device__ __forceinline__ void cp16(void* dst, const void* src) {
    uint32_t d = (uint32_t)__cvta_generic_to_shared(dst);
    asm volatile("cp.async.cg.shared.global [%0], [%1], 16;\n" :: "r"(d), "l"(src));
}
__device__ __forceinline__ void mma16816(float* d, const uint32_t* a, const uint32_t* b) {
    asm volatile(
        "mma.sync.aligned.m16n8k16.row.col.f32.bf16.bf16.f32 "
        "{%0,%1,%2,%3},{%4,%5,%6,%7},{%8,%9},{%0,%1,%2,%3};\n"
        : "+f"(d[0]), "+f"(d[1]), "+f"(d[2]), "+f"(d[3])
        : "r"(a[0]), "r"(a[1]), "r"(a[2]), "r"(a[3]), "r"(b[0]), "r"(b[1]));
}

#if HAS_TCGEN05
#define MBAR_INIT(addr, cnt) \
    asm volatile("mbarrier.init.shared.b64 [%0], %1;" :: "r"(addr), "r"(cnt) : "memory")
#define MBAR_EXPECT_TX(addr, bytes) \
    asm volatile("mbarrier.arrive.expect_tx.shared.b64 _, [%0], %1;" \
                 :: "r"(addr), "r"(bytes) : "memory")
#define MBAR_WAIT(addr, parity) do {                                        \
    asm volatile(                                                            \
        "{\n\t.reg .pred P1;\n\t"                                            \
        "WAIT_LOOP_%=:\n\t"                                                  \
        "mbarrier.try_wait.parity.acquire.cta.shared::cta.b64 P1, [%0], %1, 0x989680;\n\t" \
        "@P1 bra.uni WAIT_DONE_%=;\n\t"                                      \
        "bra.uni WAIT_LOOP_%=;\n\t"                                          \
        "WAIT_DONE_%=:\n\t}"                                                 \
        :: "r"(addr), "r"(parity) : "memory");                               \
} while (0)
#define TC_ALLOC(smem_addr, n) \
    asm volatile("tcgen05.alloc.cta_group::1.sync.aligned.shared::cta.b32 [%0], %1;" \
                 :: "r"(smem_addr), "r"(n) : "memory")
#define TC_DEALLOC(tmem, n) \
    asm volatile("tcgen05.dealloc.cta_group::1.sync.aligned.b32 %0, %1;" :: "r"(tmem), "r"(n))
#define TC_RELINQ() \
    asm volatile("tcgen05.relinquish_alloc_permit.cta_group::1.sync.aligned;")
#define TC_COMMIT(mbar) \
    asm volatile("tcgen05.commit.cta_group::1.mbarrier::arrive::one.shared::cluster.b64 [%0];" \
                 :: "r"(mbar) : "memory")
#define TC_FENCE_AFTER()  asm volatile("tcgen05.fence::after_thread_sync;" ::: "memory")
#define TC_FENCE_BEFORE() asm volatile("tcgen05.fence::before_thread_sync;" ::: "memory")
#define TC_WAIT_LD() asm volatile("tcgen05.wait::ld.sync.aligned;" ::: "memory")
#define TC_WAIT_ST() asm volatile("tcgen05.wait::st.sync.aligned;" ::: "memory")

#define TC_LD_X32(r, addr) \
    asm volatile( \
        "tcgen05.ld.sync.aligned.32x32b.x32.b32 " \
        "{%0, %1, %2, %3, %4, %5, %6, %7, %8, %9, %10, %11, %12, %13, %14, %15, " \
        " %16, %17, %18, %19, %20, %21, %22, %23, %24, %25, %26, %27, %28, %29, %30, %31}, [%32];" \
        : "=r"((r)[0]),  "=r"((r)[1]),  "=r"((r)[2]),  "=r"((r)[3]), \
          "=r"((r)[4]),  "=r"((r)[5]),  "=r"((r)[6]),  "=r"((r)[7]), \
          "=r"((r)[8]),  "=r"((r)[9]),  "=r"((r)[10]), "=r"((r)[11]), \
          "=r"((r)[12]), "=r"((r)[13]), "=r"((r)[14]), "=r"((r)[15]), \
          "=r"((r)[16]), "=r"((r)[17]), "=r"((r)[18]), "=r"((r)[19]), \
          "=r"((r)[20]), "=r"((r)[21]), "=r"((r)[22]), "=r"((r)[23]), \
          "=r"((r)[24]), "=r"((r)[25]), "=r"((r)[26]), "=r"((r)[27]), \
          "=r"((r)[28]), "=r"((r)[29]), "=r"((r)[30]), "=r"((r)[31]) \
        : "r"(addr))

#define TC_ST_X32(addr, r) \
    asm volatile( \
        "tcgen05.st.sync.aligned.32x32b.x32.b32 [%0], " \
        "{%1, %2, %3, %4, %5, %6, %7, %8, %9, %10, %11, %12, %13, %14, %15, %16, " \
        " %17, %18, %19, %20, %21, %22, %23, %24, %25, %26, %27, %28, %29, %30, %31, %32};" \
        :: "r"(addr), \
           "r"((r)[0]),  "r"((r)[1]),  "r"((r)[2]),  "r"((r)[3]), \
           "r"((r)[4]),  "r"((r)[5]),  "r"((r)[6]),  "r"((r)[7]), \
           "r"((r)[8]),  "r"((r)[9]),  "r"((r)[10]), "r"((r)[11]), \
           "r"((r)[12]), "r"((r)[13]), "r"((r)[14]), "r"((r)[15]), \
           "r"((r)[16]), "r"((r)[17]), "r"((r)[18]), "r"((r)[19]), \
           "r"((r)[20]), "r"((r)[21]), "r"((r)[22]), "r"((r)[23]), \
           "r"((r)[24]), "r"((r)[25]), "r"((r)[26]), "r"((r)[27]), \
           "r"((r)[28]), "r"((r)[29]), "r"((r)[30]), "r"((r)[31]) \
        : "memory")

#define TC_ST_X16(addr, r) \
    asm volatile( \
        "tcgen05.st.sync.aligned.32x32b.x16.b32 [%0], " \
        "{%1, %2, %3, %4, %5, %6, %7, %8, %9, %10, %11, %12, %13, %14, %15, %16};" \
        :: "r"(addr), \
           "r"((r)[0]),  "r"((r)[1]),  "r"((r)[2]),  "r"((r)[3]), \
           "r"((r)[4]),  "r"((r)[5]),  "r"((r)[6]),  "r"((r)[7]), \
           "r"((r)[8]),  "r"((r)[9]),  "r"((r)[10]), "r"((r)[11]), \
           "r"((r)[12]), "r"((r)[13]), "r"((r)[14]), "r"((r)[15]) \
        : "memory")

__device__ __forceinline__ void tc_mma_ss_f16(
    uint32_t d_tmem, uint64_t a_desc, uint64_t b_desc, uint32_t idesc, uint32_t en)
{
    asm volatile(
        "{\n\t.reg .pred p;\n\t"
        "setp.ne.u32 p, %4, 0;\n\t"
        "tcgen05.mma.cta_group::1.kind::f16 [%0], %1, %2, %3, {%5, %5, %5, %5}, p;\n\t"
        "}"
        :: "r"(d_tmem), "l"(a_desc), "l"(b_desc), "r"(idesc), "r"(en), "r"(0u)
        : "memory");
}
__device__ __forceinline__ void tc_mma_ts_f16(
    uint32_t d_tmem, uint32_t a_tmem, uint64_t b_desc, uint32_t idesc, uint32_t en)
{
    asm volatile(
        "{\n\t.reg .pred p;\n\t"
        "setp.ne.u32 p, %4, 0;\n\t"
        "tcgen05.mma.cta_group::1.kind::f16 [%0], [%1], %2, %3, {%5, %5, %5, %5}, p;\n\t"
        "}"
        :: "r"(d_tmem), "r"(a_tmem), "l"(b_desc), "r"(idesc), "r"(en), "r"(0u)
        : "memory");
}
__device__ __forceinline__ uint64_t make_desc_sw128(uint32_t smem_addr) {
    return ((uint64_t)2 << 61) | ((uint64_t)1 << 46) | ((uint64_t)64 << 32)
         | ((uint64_t)1 << 16) | ((uint64_t)(smem_addr >> 4) & 0x3FFF);
}
__device__ __forceinline__ void tma2d(uint32_t smem_addr, const CUtensorMap* tmap,
                                      int ck, int crow, uint32_t mbar)
{
    asm volatile(
        "cp.async.bulk.tensor.2d.shared::cta.global.tile.mbarrier::complete_tx::bytes "
        "[%0], [%1, {%2, %3}], [%4];"
        :: "r"(smem_addr), "l"(tmap), "r"(ck), "r"(crow), "r"(mbar) : "memory");
}
#endif

// ---------------------------------------------------------------------------
// Dual-path GEMM: TMA + tcgen05 cg1, 128x256x64, 2 stages.
// R16 change: done-wait deferred by one tile so MMA(kt+1) queues behind
// MMA(kt) and each load gets a 2-tile window (tensor-bound steady state).
// ---------------------------------------------------------------------------
#define GBM 128
#define GBN 256
#define TBK 64
#define ST_A 16384
#define ST_B 32768
#define TSTAGE (2 * ST_A + 2 * ST_B)   // 98304
#define FBK 32
#define FLDA 40
#define FSSZ (128 * FLDA)
#define GEMM_SMEM (1024 + 2 * TSTAGE)
#define GEMM_IDESC 0x8400490u

__global__ __launch_bounds__(256) void gemm_dual(
    const bf16* __restrict__ Ah, const bf16* __restrict__ Al,
    const bf16* __restrict__ Bh, const bf16* __restrict__ Bl,
    const __grid_constant__ CUtensorMap tmAh,
    const __grid_constant__ CUtensorMap tmAl,
    const __grid_constant__ CUtensorMap tmBh,
    const __grid_constant__ CUtensorMap tmBl,
    float* __restrict__ Cc, int M, int N, int K)
{
#if HAS_TCGEN05
    extern __shared__ __align__(1024) char smem[];
    uint32_t sbase = (uint32_t)__cvta_generic_to_shared(smem);
    int tid = threadIdx.x, warp = tid >> 5, lane = tid & 31;
    int bx = blockIdx.x, by = blockIdx.y;
    const int ktiles = K / TBK;   // >= 2 for all our shapes

    if (tid == 0) {
        MBAR_INIT(sbase + 16, 1);   // full[0]
        MBAR_INIT(sbase + 24, 1);   // full[1]
        MBAR_INIT(sbase + 32, 1);   // done[0]
        MBAR_INIT(sbase + 40, 1);   // done[1]
    }
    if (warp == 0) TC_ALLOC(sbase, 256);
    __syncthreads();
    uint32_t tmem;
    asm volatile("ld.shared.b32 %0, [%1];" : "=r"(tmem) : "r"(sbase));

    auto issue_load = [&](int kt) {
        if (kt < ktiles && tid == 0) {
            int s = kt & 1;
            uint32_t st = sbase + 1024 + (uint32_t)s * TSTAGE;
            uint32_t mb = sbase + 16 + (uint32_t)s * 8;
            MBAR_EXPECT_TX(mb, (uint32_t)TSTAGE);
            int k0 = kt * TBK;
            tma2d(st,                  &tmAh, k0, by * GBM, mb);
            tma2d(st + ST_A,           &tmAl, k0, by * GBM, mb);
            tma2d(st + 2 * ST_A,       &tmBh, k0, bx * GBN, mb);
            tma2d(st + 2 * ST_A + ST_B,&tmBl, k0, bx * GBN, mb);
        }
    };

    auto issue_mma = [&](int kt) {
        uint32_t a0 = sbase + 1024 + (uint32_t)(kt & 1) * TSTAGE;
        uint64_t dAh = make_desc_sw128(a0);
        uint64_t dAl = make_desc_sw128(a0 + ST_A);
        uint64_t dBh = make_desc_sw128(a0 + 2 * ST_A);
        uint64_t dBl = make_desc_sw128(a0 + 2 * ST_A + ST_B);
        #pragma unroll
        for (int ks = 0; ks < 4; ks++) {
            tc_mma_ss_f16(tmem, dAh + ks * 2, dBh + ks * 2, GEMM_IDESC,
                          (kt > 0 || ks > 0) ? 1u : 0u);
            tc_mma_ss_f16(tmem, dAh + ks * 2, dBl + ks * 2, GEMM_IDESC, 1u);
            tc_mma_ss_f16(tmem, dAl + ks * 2, dBh + ks * 2, GEMM_IDESC, 1u);
        }
        TC_COMMIT(sbase + 32 + (uint32_t)(kt & 1) * 8);
    };

    issue_load(0);
    issue_load(1);

    // tile 0: dispatch without waiting on any done
    MBAR_WAIT(sbase + 16, 0u);
    if (tid == 0) issue_mma(0);

    for (int kt = 1; kt < ktiles; kt++) {
        int s = kt & 1;
        MBAR_WAIT(sbase + 16 + (uint32_t)s * 8, (uint32_t)((kt >> 1) & 1));
        if (tid == 0) issue_mma(kt);
        // buffer (kt+1)&1 == (kt-1)&1 is freed once MMA(kt-1) completes
        MBAR_WAIT(sbase + 32 + (uint32_t)((kt - 1) & 1) * 8,
                  (uint32_t)(((kt - 1) >> 1) & 1));
        issue_load(kt + 1);
    }

    MBAR_WAIT(sbase + 32 + (uint32_t)((ktiles - 1) & 1) * 8,
              (uint32_t)(((ktiles - 1) >> 1) & 1));
    TC_FENCE_AFTER();

    int sp = warp & 3, chf = warp >> 2;
    #pragma unroll
    for (int cc = 0; cc < 4; cc++) {
        uint32_t dr[32];
        TC_LD_X32(dr, tmem + chf * 128 + cc * 32);
        TC_WAIT_LD();
        int row = by * GBM + sp * 32 + lane;
        int col = bx * GBN + chf * 128 + cc * 32;
        float* o = Cc + (size_t)row * N + col;
        #pragma unroll
        for (int q = 0; q < 8; q++)
            *(float4*)(o + q * 4) = make_float4(
                __uint_as_float(dr[4 * q]),     __uint_as_float(dr[4 * q + 1]),
                __uint_as_float(dr[4 * q + 2]), __uint_as_float(dr[4 * q + 3]));
    }
    __syncthreads();
    if (warp == 0) {
        TC_RELINQ();
        TC_DEALLOC(tmem, 256);
    }
#else
    // mma.sync fallback (PTX-only pass; runtime uses sm_103a cubin).
    extern __shared__ bf16 sm[];
    int tid = threadIdx.x;
    int by = blockIdx.y;
    int warp = tid >> 5, lane = tid & 31;
    int wm = (warp >> 2) * 64, wn = (warp & 3) * 32;
    int r = lane >> 2, c = lane & 3;

    for (int half = 0; half < 2; half++) {
        int bxe = blockIdx.x * 2 + half;
        const bf16* gAh = Ah + (size_t)(by * GBM) * K;
        const bf16* gAl = Al + (size_t)(by * GBM) * K;
        const bf16* gBh = Bh + (size_t)(bxe * 128) * K;
        const bf16* gBl = Bl + (size_t)(bxe * 128) * K;

        float acc[4][4][4];
        #pragma unroll
        for (int i = 0; i < 4; i++)
            #pragma unroll
            for (int j = 0; j < 4; j++)
                #pragma unroll
                for (int e = 0; e < 4; e++) acc[i][j][e] = 0.f;

        const int k_tiles = K / FBK;

        auto issue = [&](int stage, int kt) {
            if (kt < k_tiles) {
                size_t k0 = (size_t)kt * FBK;
                bf16* base = sm + stage * 4 * FSSZ;
                #pragma unroll
                for (int p = 0; p < 2; p++) {
                    int ci = tid + p * 256;
                    int row = ci >> 2, c16 = ci & 3;
                    int so = row * FLDA + c16 * 8;
                    size_t go = (size_t)row * K + k0 + c16 * 8;
                    cp16(base + so,            gAh + go);
                    cp16(base + FSSZ + so,     gAl + go);
                    cp16(base + 2 * FSSZ + so, gBh + go);
                    cp16(base + 3 * FSSZ + so, gBl + go);
                }
            }
            asm volatile("cp.async.commit_group;\n" ::);
        };

        #pragma unroll
        for (int s = 0; s < 2; s++) issue(s, s);

        for (int kt = 0; kt < k_tiles; kt++) {
            asm volatile("cp.async.wait_group 1;\n" ::);
            __syncthreads();
            issue((kt + 2) % 3, kt + 2);

            const uint32_t* wAh = (const uint32_t*)(sm + (kt % 3) * 4 * FSSZ);
            const uint32_t* wAl = wAh + FSSZ / 2;
            const uint32_t* wBh = wAh + FSSZ;
            const uint32_t* wBl = wAh + 3 * (FSSZ / 2);

            #pragma unroll
            for (int ks = 0; ks < 2; ks++) {
                int kw = ks * 8;
                uint32_t a_h[4][4], a_l[4][4], b_h[4][2], b_l[4][2];
                #pragma unroll
                for (int i = 0; i < 4; i++) {
                    int r0 = (wm + i * 16 + r) * 20 + kw + c;
                    int r1 = r0 + 8 * 20;
                    a_h[i][0] = wAh[r0];     a_h[i][1] = wAh[r1];
                    a_h[i][2] = wAh[r0 + 4]; a_h[i][3] = wAh[r1 + 4];
                    a_l[i][0] = wAl[r0];     a_l[i][1] = wAl[r1];
                    a_l[i][2] = wAl[r0 + 4]; a_l[i][3] = wAl[r1 + 4];
                }
                #pragma unroll
                for (int j = 0; j < 4; j++) {
                    int n0 = (wn + j * 8 + r) * 20 + kw + c;
                    b_h[j][0] = wBh[n0]; b_h[j][1] = wBh[n0 + 4];
                    b_l[j][0] = wBl[n0]; b_l[j][1] = wBl[n0 + 4];
                }
                #pragma unroll
                for (int i = 0; i < 4; i++)
                    #pragma unroll
                    for (int j = 0; j < 4; j++) {
                        mma16816(acc[i][j], a_h[i], b_h[j]);
                        mma16816(acc[i][j], a_h[i], b_l[j]);
                        mma16816(acc[i][j], a_l[i], b_h[j]);
                    }
            }
            __syncthreads();
        }

        #pragma unroll
        for (int i = 0; i < 4; i++)
            #pragma unroll
            for (int j = 0; j < 4; j++) {
                int row = by * GBM + wm + i * 16 + r;
                int col = bxe * 128 + wn + j * 8 + 2 * c;
                *(float2*)(Cc + (size_t)row * N + col) =
                    make_float2(acc[i][j][0], acc[i][j][1]);
                *(float2*)(Cc + (size_t)(row + 8) * N + col) =
                    make_float2(acc[i][j][2], acc[i][j][3]);
            }
        __syncthreads();
    }
#endif
}

// ---------------------------------------------------------------------------
// tcgen05 flash attention — exact R12 version (passing at 990us)
// TMEM: O@0(128), Qh@128(64), Ql@192(64), S0@256, S1@320, Ph@384(32), Pl@416(32)
// ---------------------------------------------------------------------------
#define AK_B 16384
#define ASTAGE (4 * AK_B)
#define ATTN_TC_SMEM (1024 + 3 * ASTAGE)
#define IDESC_S  0x8100490u
#define IDESC_PV 0x8200490u

__global__ __launch_bounds__(256) void attn_tc(
    const bf16* __restrict__ qh, const bf16* __restrict__ ql,
    const bf16* __restrict__ kh_, const bf16* __restrict__ kl_,
    const bf16* __restrict__ vth, const bf16* __restrict__ vtl,
    bf16* __restrict__ eh, bf16* __restrict__ el)
{
#if HAS_TCGEN05
    extern __shared__ __align__(1024) char smem[];
    __shared__ float sL[2][128];
    uint32_t sbase = (uint32_t)__cvta_generic_to_shared(smem);
    int tid = threadIdx.x, warp = tid >> 5, lane = tid & 31;
    int b = blockIdx.z, n = blockIdx.y, khd = n >> 2;
    int q0 = blockIdx.x * 128, bT = b * T_;
    const int NT = T_ / 64;

    if (tid == 0) {
        MBAR_INIT(sbase + 8, 1);
        MBAR_INIT(sbase + 16, 1);
        MBAR_INIT(sbase + 24, 1);
    }
    if (warp == 0) TC_ALLOC(sbase, 512);
    __syncthreads();
    uint32_t tmem;
    asm volatile("ld.shared.b32 %0, [%1];" : "=r"(tmem) : "r"(sbase));

    auto issue_k = [&](int tile) {
        if (tile < NT) {
            int s0 = tile * 64;
            char* st = smem + 1024 + (tile % 3) * ASTAGE;
            #pragma unroll
            for (int a = 0; a < 2; a++) {
                const bf16* g = (a ? kl_ : kh_);
                char* base = st + a * AK_B;
                #pragma unroll
                for (int it = 0; it < 4; it++) {
                    int idx = tid + it * 256;
                    int s = idx >> 4, ch = idx & 15;
                    uint32_t off = (uint32_t)((s >> 3) * 1024 + (ch >> 3) * 8192
                                            + (s & 7) * 128 + (ch & 7) * 16);
                    off ^= ((off >> 3) & 0x70);
                    cp16(base + off, g + (size_t)(bT + s0 + s) * KH_ + khd * 128 + ch * 8);
                }
            }
        }
        asm volatile("cp.async.commit_group;\n" ::);
    };
    auto issue_v = [&](int tile) {
        if (tile < NT) {
            int s0 = tile * 64;
            char* st = smem + 1024 + (tile % 3) * ASTAGE;
            #pragma unroll
            for (int a = 0; a < 2; a++) {
                const bf16* g = (a ? vtl : vth);
                char* base = st + 2 * AK_B + a * AK_B;
                #pragma unroll
                for (int it = 0; it < 4; it++) {
                    int idx = tid + it * 256;
                    int h = idx >> 3, tch = idx & 7;
                    uint32_t off = (uint32_t)((h >> 3) * 1024 + (h & 7) * 128 + tch * 16);
                    off ^= ((off >> 3) & 0x70);
                    cp16(base + off,
                         g + ((size_t)(b * 4 + khd) * 128 + h) * T_ + s0 + tch * 8);
                }
            }
        }
        asm volatile("cp.async.commit_group;\n" ::);
    };

    auto issue_S = [&](int tile) {
        uint32_t kb = sbase + 1024 + (uint32_t)(tile % 3) * ASTAGE;
        uint64_t dKh = make_desc_sw128(kb);
        uint64_t dKl = make_desc_sw128(kb + AK_B);
        uint32_t sdst = tmem + 256 + (uint32_t)(tile & 1) * 64;
        #pragma unroll
        for (int ks = 0; ks < 8; ks++) {
            uint64_t koff = (ks < 4) ? (uint64_t)(ks * 2)
                                     : (uint64_t)(512 + (ks - 4) * 2);
            uint32_t aH = tmem + 128 + ks * 8, aL = tmem + 192 + ks * 8;
            tc_mma_ts_f16(sdst, aH, dKh + koff, IDESC_S, ks > 0 ? 1u : 0u);
            tc_mma_ts_f16(sdst, aH, dKl + koff, IDESC_S, 1u);
            tc_mma_ts_f16(sdst, aL, dKh + koff, IDESC_S, 1u);
        }
        TC_COMMIT(sbase + 8 + (uint32_t)(tile & 1) * 8);
    };

    issue_k(0);
    issue_v(0);
    issue_k(1);
    issue_v(1);

    if (tid < 128) {
        uint32_t woffq = (uint32_t)(tid >> 5) << 21;
        uint32_t qr[32];
        const uint4* srcA = (const uint4*)(qh + (size_t)(bT + q0 + tid) * NH_ + n * 128);
        const uint4* srcB = (const uint4*)(ql + (size_t)(bT + q0 + tid) * NH_ + n * 128);
        #pragma unroll
        for (int i = 0; i < 8; i++) {
            uint4 v = srcA[i];
            qr[4*i] = v.x; qr[4*i+1] = v.y; qr[4*i+2] = v.z; qr[4*i+3] = v.w;
        }
        TC_ST_X32(tmem + 128 + woffq, qr);
        #pragma unroll
        for (int i = 0; i < 8; i++) {
            uint4 v = srcA[i + 8];
            qr[4*i] = v.x; qr[4*i+1] = v.y; qr[4*i+2] = v.z; qr[4*i+3] = v.w;
        }
        TC_ST_X32(tmem + 160 + woffq, qr);
        #pragma unroll
        for (int i = 0; i < 8; i++) {
            uint4 v = srcB[i];
            qr[4*i] = v.x; qr[4*i+1] = v.y; qr[4*i+2] = v.z; qr[4*i+3] = v.w;
        }
        TC_ST_X32(tmem + 192 + woffq, qr);
        #pragma unroll
        for (int i = 0; i < 8; i++) {
            uint4 v = srcB[i + 8];
            qr[4*i] = v.x; qr[4*i+1] = v.y; qr[4*i+2] = v.z; qr[4*i+3] = v.w;
        }
        TC_ST_X32(tmem + 224 + woffq, qr);
        TC_WAIT_ST();
    }
    TC_FENCE_BEFORE();
    asm volatile("cp.async.wait_group 2;\n" ::);
    __syncthreads();

    if (tid == 0) {
        TC_FENCE_AFTER();
        asm volatile("fence.proxy.async.shared::cta;" ::: "memory");
        issue_S(0);
    }

    int chalf = warp >> 2;
    int row = (warp & 3) * 32 + lane;
    uint32_t woff = (uint32_t)(warp & 3) << 21;
    float li = 0.f;

    for (int t = 0; t < NT; t++) {
        MBAR_WAIT(sbase + 8 + (uint32_t)(t & 1) * 8, (uint32_t)((t >> 1) & 1));
        TC_FENCE_AFTER();
        issue_k(t + 2);

        asm volatile("cp.async.wait_group 1;\n" ::);
        __syncthreads();
        if (tid == 0 && t + 1 < NT) {
            asm volatile("fence.proxy.async.shared::cta;" ::: "memory");
            issue_S(t + 1);
        }

        uint32_t sr[32];
        TC_LD_X32(sr, tmem + 256 + (uint32_t)(t & 1) * 64 + chalf * 32);
        TC_WAIT_LD();
        float pv[32];
        float lsum = 0.f;
        #pragma unroll
        for (int i = 0; i < 32; i++) {
            pv[i] = __expf(__uint_as_float(sr[i]));
            lsum += pv[i];
        }
        li += lsum;
        uint32_t ph[16], pl[16];
        #pragma unroll
        for (int j = 0; j < 16; j++) {
            float p0 = pv[2*j], p1 = pv[2*j+1];
            bf16 h0 = __float2bfloat16(p0), h1 = __float2bfloat16(p1);
            __nv_bfloat162 hp = {h0, h1};
            __nv_bfloat162 lp = {__float2bfloat16(p0 - __bfloat162float(h0)),
                                 __float2bfloat16(p1 - __bfloat162float(h1))};
            ph[j] = *(uint32_t*)&hp;
            pl[j] = *(uint32_t*)&lp;
        }

        if (t >= 1) MBAR_WAIT(sbase + 24, (uint32_t)((t - 1) & 1));
        TC_FENCE_AFTER();

        issue_v(t + 2);

        TC_ST_X16(tmem + 384 + chalf * 16 + woff, ph);
        TC_ST_X16(tmem + 416 + chalf * 16 + woff, pl);
        TC_WAIT_ST();
        TC_FENCE_BEFORE();
        __syncthreads();

        if (tid == 0) {
            TC_FENCE_AFTER();
            asm volatile("fence.proxy.async.shared::cta;" ::: "memory");
            uint32_t vb = sbase + 1024 + (uint32_t)(t % 3) * ASTAGE + 2 * AK_B;
            uint64_t dVh = make_desc_sw128(vb);
            uint64_t dVl = make_desc_sw128(vb + AK_B);
            #pragma unroll
            for (int ks = 0; ks < 4; ks++) {
                uint32_t aH = tmem + 384 + ks * 8, aL = tmem + 416 + ks * 8;
                tc_mma_ts_f16(tmem, aH, dVh + ks * 2, IDESC_PV,
                              (t > 0 || ks > 0) ? 1u : 0u);
                tc_mma_ts_f16(tmem, aH, dVl + ks * 2, IDESC_PV, 1u);
                tc_mma_ts_f16(tmem, aL, dVh + ks * 2, IDESC_PV, 1u);
            }
            TC_COMMIT(sbase + 24);
        }
    }

    sL[chalf][row] = li;
    __syncthreads();
    float inv = 1.f / (sL[0][row] + sL[1][row]);

    MBAR_WAIT(sbase + 24, (uint32_t)((NT - 1) & 1));
    TC_FENCE_AFTER();

    uint32_t o0[32], o1[32];
    TC_LD_X32(o0, tmem + chalf * 64);
    TC_LD_X32(o1, tmem + chalf * 64 + 32);
    TC_WAIT_LD();

    size_t obase = (size_t)(bT + q0 + row) * NH_ + n * 128 + chalf * 64;
    #pragma unroll
    for (int j = 0; j < 16; j++) {
        float v0 = __uint_as_float(j < 8 ? o0[4*(j&7)]   : o1[4*(j&7)])   * inv;
        float v1 = __uint_as_float(j < 8 ? o0[4*(j&7)+1] : o1[4*(j&7)+1]) * inv;
        float v2 = __uint_as_float(j < 8 ? o0[4*(j&7)+2] : o1[4*(j&7)+2]) * inv;
        float v3 = __uint_as_float(j < 8 ? o0[4*(j&7)+3] : o1[4*(j&7)+3]) * inv;
        bf16 h0 = __float2bfloat16(v0), h1 = __float2bfloat16(v1);
        bf16 h2 = __float2bfloat16(v2), h3 = __float2bfloat16(v3);
        __nv_bfloat162 hp0 = {h0, h1}, hp1 = {h2, h3};
        __nv_bfloat162 lp0 = {__float2bfloat16(v0 - __bfloat162float(h0)),
                              __float2bfloat16(v1 - __bfloat162float(h1))};
        __nv_bfloat162 lp1 = {__float2bfloat16(v2 - __bfloat162float(h2)),
                              __float2bfloat16(v3 - __bfloat162float(h3))};
        int colo = (j & 7) * 4 + (j < 8 ? 0 : 32);
        *(uint2*)(eh + obase + colo) = make_uint2(*(uint32_t*)&hp0, *(uint32_t*)&hp1);
        *(uint2*)(el + obase + colo) = make_uint2(*(uint32_t*)&lp0, *(uint32_t*)&lp1);
    }

    __syncthreads();
    if (warp == 0) {
        TC_RELINQ();
        TC_DEALLOC(tmem, 512);
    }
#endif
}

// ---------------------------------------------------------------------------
// Prep kernels (unchanged)
// ---------------------------------------------------------------------------
__global__ __launch_bounds__(256) void split_f32(
    const float* __restrict__ src, bf16* __restrict__ hi, bf16* __restrict__ lo,
    size_t n4)
{
    size_t i = (size_t)blockIdx.x * blockDim.x + threadIdx.x;
    if (i >= n4) return;
    float4 v = *(const float4*)(src + i * 4);
    bf16 h0 = __float2bfloat16(v.x), h1 = __float2bfloat16(v.y);
    bf16 h2 = __float2bfloat16(v.z), h3 = __float2bfloat16(v.w);
    bf16 l0 = __float2bfloat16(v.x - __bfloat162float(h0));
    bf16 l1 = __float2bfloat16(v.y - __bfloat162float(h1));
    bf16 l2 = __float2bfloat16(v.z - __bfloat162float(h2));
    bf16 l3 = __float2bfloat16(v.w - __bfloat162float(h3));
    __nv_bfloat162 hp0 = {h0, h1}, hp1 = {h2, h3};
    __nv_bfloat162 lp0 = {l0, l1}, lp1 = {l2, l3};
    *(uint2*)(hi + i * 4) = make_uint2(*(unsigned int*)&hp0, *(unsigned int*)&hp1);
    *(uint2*)(lo + i * 4) = make_uint2(*(unsigned int*)&lp0, *(unsigned int*)&lp1);
}

__global__ __launch_bounds__(256) void tsplit_wc(
    const float* __restrict__ Wq, const float* __restrict__ Wk,
    const float* __restrict__ Wv, bf16* __restrict__ hi, bf16* __restrict__ lo)
{
    __shared__ float t[32][33];
    int kb = blockIdx.y * 32;
    int nb = blockIdx.x * 32;
    const float* W;
    int srcN, srcCol;
    if (nb < NH_)            { W = Wq; srcN = NH_; srcCol = nb; }
    else if (nb < NH_ + KH_) { W = Wk; srcN = KH_; srcCol = nb - NH_; }
    else                     { W = Wv; srcN = KH_; srcCol = nb - NH_ - KH_; }
    #pragma unroll
    for (int i = 0; i < 4; i++)
        t[threadIdx.y + 8 * i][threadIdx.x] =
            W[(size_t)(kb + threadIdx.y + 8 * i) * srcN + srcCol + threadIdx.x];
    __syncthreads();
    #pragma unroll
    for (int i = 0; i < 4; i++) {
        float f = t[threadIdx.x][threadIdx.y + 8 * i];
        bf16 h = __float2bfloat16(f);
        size_t idx = (size_t)(nb + threadIdx.y + 8 * i) * C_ + kb + threadIdx.x;
        hi[idx] = h;
        lo[idx] = __float2bfloat16(f - __bfloat162float(h));
    }
}

__global__ __launch_bounds__(256) void tsplit(
    const float* __restrict__ W, bf16* __restrict__ hi, bf16* __restrict__ lo,
    int K, int N)
{
    __shared__ float t[32][33];
    int kb = blockIdx.y * 32, nb = blockIdx.x * 32;
    #pragma unroll
    for (int i = 0; i < 4; i++)
        t[threadIdx.y + 8 * i][threadIdx.x] =
            W[(size_t)(kb + threadIdx.y + 8 * i) * N + nb + threadIdx.x];
    __syncthreads();
    #pragma unroll
    for (int i = 0; i < 4; i++) {
        float f = t[threadIdx.x][threadIdx.y + 8 * i];
        bf16 h = __float2bfloat16(f);
        size_t idx = (size_t)(nb + threadIdx.y + 8 * i) * K + kb + threadIdx.x;
        hi[idx] = h;
        lo[idx] = __float2bfloat16(f - __bfloat162float(h));
    }
}

__global__ __launch_bounds__(256) void vtsplit(
    const float* __restrict__ qkv, bf16* __restrict__ hi, bf16* __restrict__ lo)
{
    __shared__ float t[32][33];
    int t0 = blockIdx.x * 32, h0 = blockIdx.y * 32;
    int bz = blockIdx.z;
    int b = bz >> 2, kh = bz & 3;
    #pragma unroll
    for (int i = 0; i < 4; i++)
        t[threadIdx.y + 8 * i][threadIdx.x] =
            qkv[(size_t)(b * T_ + t0 + threadIdx.y + 8 * i) * QKV_ + 2560 + kh * 128 + h0 + threadIdx.x];
    __syncthreads();
    #pragma unroll
    for (int i = 0; i < 4; i++) {
        float f = t[threadIdx.x][threadIdx.y + 8 * i];
        bf16 h = __float2bfloat16(f);
        size_t idx = ((size_t)bz * 128 + h0 + threadIdx.y + 8 * i) * T_ + t0 + threadIdx.x;
        hi[idx] = h;
        lo[idx] = __float2bfloat16(f - __bfloat162float(h));
    }
}

__global__ __launch_bounds__(256) void rms_rope_split(
    const float* __restrict__ in, int inoff,
    bf16* __restrict__ outh, bf16* __restrict__ outl,
    int width, int nheads, float outscale)
{
    int row = blockIdx.x;
    int t = row % T_;
    const float* ptr = in + (size_t)row * QKV_ + inoff;

    float ss = 0.f;
    for (int i = threadIdx.x; i < width; i += 256) {
        float v = ptr[i];
        ss += v * v;
    }
    #pragma unroll
    for (int o = 16; o; o >>= 1) ss += __shfl_xor_sync(0xffffffffu, ss, o);
    __shared__ float red[8];
    if ((threadIdx.x & 31) == 0) red[threadIdx.x >> 5] = ss;
    __syncthreads();
    float tot = red[0] + red[1] + red[2] + red[3] + red[4] + red[5] + red[6] + red[7];
    float rs = rsqrtf(tot / (float)width + 1e-6f) * outscale;

    int npairs = nheads * 64;
    const double TWO_PI = 6.283185307179586476925286766559;
    bf16* oh = outh + (size_t)row * width;
    bf16* ol = outl + (size_t)row * width;
    for (int p = threadIdx.x; p < npairs; p += 256) {
        int head = p >> 6;
        int hp = p & 63;
        float inv = __expf(-(float)hp * (9.210340371976184f / 64.f));
        float theta = (float)t * inv;
        double td = (double)theta * (1.0 / TWO_PI);
        double frac = td - floor(td);
        if (frac > 0.5) frac -= 1.0;
        float redang = (float)(frac * TWO_PI);
        float s, cc;
        sincosf(redang, &s, &cc);

        int base = head * H_;
        float x1 = ptr[base + hp] * rs;
        float x2 = ptr[base + hp + 64] * rs;
        float y1 = x1 * cc - x2 * s;
        float y2 = x2 * cc + x1 * s;
        bf16 h1 = __float2bfloat16(y1), h2 = __float2bfloat16(y2);
        oh[base + hp]      = h1;
        oh[base + hp + 64] = h2;
        ol[base + hp]      = __float2bfloat16(y1 - __bfloat162float(h1));
        ol[base + hp + 64] = __float2bfloat16(y2 - __bfloat162float(h2));
    }
}

// ---------------------------------------------------------------------------
// Host: tensormap encode via runtime-resolved driver entry point
// ---------------------------------------------------------------------------
typedef CUresult (*PFN_tmapEncode)(
    CUtensorMap*, CUtensorMapDataType, unsigned int, void*,
    const unsigned long long*, const unsigned long long*,
    const unsigned int*, const unsigned int*,
    CUtensorMapInterleave, CUtensorMapSwizzle,
    CUtensorMapL2promotion, CUtensorMapFloatOOBfill);

static void make_tmap(CUtensorMap* tm, void* ptr, int rows, int K, int boxRows)
{
    PFN_tmapEncode enc = nullptr;
    cudaDriverEntryPointQueryResult st;
    cudaGetDriverEntryPoint("cuTensorMapEncodeTiled", (void**)&enc,
                            cudaEnableDefault, &st);
    unsigned long long dims[2]    = {(unsigned long long)K, (unsigned long long)rows};
    unsigned long long strides[1] = {(unsigned long long)K * 2};
    unsigned int box[2] = {64u, (unsigned int)boxRows};
    unsigned int es[2]  = {1u, 1u};
    enc(tm, CU_TENSOR_MAP_DATA_TYPE_BFLOAT16, 2, ptr, dims, strides, box, es,
        CU_TENSOR_MAP_INTERLEAVE_NONE, CU_TENSOR_MAP_SWIZZLE_128B,
        CU_TENSOR_MAP_L2_PROMOTION_L2_128B, CU_TENSOR_MAP_FLOAT_OOB_FILL_NONE);
}

// ---------------------------------------------------------------------------
extern "C" void kernel_launch(void* const* d_in, const int* in_sizes, int n_in,
                              void* d_out, int out_size)
{
    const float* x    = (const float*)d_in[0];
    const float* Wq   = (const float*)d_in[1];
    const float* Wk   = (const float*)d_in[2];
    const float* Wv   = (const float*)d_in[3];
    const float* Wout = (const float*)d_in[4];
    float* out = (float*)d_out;

    float* qkv;
    cudaGetSymbolAddress((void**)&qkv, g_qkv);
    bf16 *xh, *xl, *eh, *el, *qsh, *qsl, *ksh, *ksl, *vth, *vtl;
    bf16 *wch, *wcl, *woh, *wol;
    cudaGetSymbolAddress((void**)&xh, g_x_hi);   cudaGetSymbolAddress((void**)&xl, g_x_lo);
    cudaGetSymbolAddress((void**)&eh, g_e_hi);   cudaGetSymbolAddress((void**)&el, g_e_lo);
    cudaGetSymbolAddress((void**)&qsh, g_qh);    cudaGetSymbolAddress((void**)&qsl, g_ql);
    cudaGetSymbolAddress((void**)&ksh, g_kh);    cudaGetSymbolAddress((void**)&ksl, g_kl);
    cudaGetSymbolAddress((void**)&vth, g_vth);   cudaGetSymbolAddress((void**)&vtl, g_vtl);
    cudaGetSymbolAddress((void**)&wch, g_Wc_hi); cudaGetSymbolAddress((void**)&wcl, g_Wc_lo);
    cudaGetSymbolAddress((void**)&woh, g_Wo_hi); cudaGetSymbolAddress((void**)&wol, g_Wo_lo);

    cudaFuncSetAttribute(gemm_dual, cudaFuncAttributeMaxDynamicSharedMemorySize,
                         GEMM_SMEM);
    cudaFuncSetAttribute(attn_tc, cudaFuncAttributeMaxDynamicSharedMemorySize,
                         ATTN_TC_SMEM);

    // tensormaps (host-side, by-value kernel params; graph-safe)
    CUtensorMap tmXh, tmXl, tmWch, tmWcl, tmEh, tmEl, tmWoh, tmWol;
    make_tmap(&tmXh,  xh,  M_,   C_,  128);
    make_tmap(&tmXl,  xl,  M_,   C_,  128);
    make_tmap(&tmWch, wch, QKV_, C_,  256);
    make_tmap(&tmWcl, wcl, QKV_, C_,  256);
    make_tmap(&tmEh,  eh,  M_,   NH_, 128);
    make_tmap(&tmEl,  el,  M_,   NH_, 128);
    make_tmap(&tmWoh, woh, C_,   NH_, 256);
    make_tmap(&tmWol, wol, C_,   NH_, 256);

    // prep
    split_f32<<<(int)((M_ * (size_t)C_ / 4 + 255) / 256), 256>>>(x, xh, xl, (size_t)M_ * C_ / 4);
    tsplit_wc<<<dim3(QKV_ / 32, C_ / 32), dim3(32, 8)>>>(Wq, Wk, Wv, wch, wcl);
    tsplit<<<dim3(C_ / 32, NH_ / 32), dim3(32, 8)>>>(Wout, woh, wol, NH_, C_);

    // launch 4: fused QKV projection (tcgen05 + TMA, deferred done-wait) — profiled
    gemm_dual<<<dim3(QKV_ / GBN, M_ / GBM), 256, GEMM_SMEM>>>(
        xh, xl, wch, wcl, tmXh, tmXl, tmWch, tmWcl, qkv, M_, QKV_, C_);

    // norm + rope -> split bf16 ; V transpose+split
    rms_rope_split<<<M_, 256>>>(qkv, 0,    qsh, qsl, NH_, NHEADS, 0.08838834764831845f);
    rms_rope_split<<<M_, 256>>>(qkv, 2048, ksh, ksl, KH_, 4, 1.0f);
    vtsplit<<<dim3(T_ / 32, 4, 16), dim3(32, 8)>>>(qkv, vth, vtl);

    // attention (tcgen05, exact R12 pipeline)
    dim3 gAttn(T_ / 128, NHEADS, B_);
    attn_tc<<<gAttn, 256, ATTN_TC_SMEM>>>(qsh, qsl, ksh, ksl, vth, vtl, eh, el);

    // output projection (tcgen05 + TMA, deferred done-wait)
    gemm_dual<<<dim3(C_ / GBN, M_ / GBM), 256, GEMM_SMEM>>>(
        eh, el, woh, wol, tmEh, tmEl, tmWoh, tmWol, out, M_, C_, NH_);
}

// round 17
// speedup vs baseline: 1.1588x; 1.1588x over previous
#include <cuda_runtime.h>
#include <cuda.h>
#include <cuda_bf16.h>
#include <cstdint>
#include <math.h>

#define B_ 4
#define T_ 2048
#define C_ 2048
#define NH_ 2048
#define KH_ 512
#define QKV_ 3072      // NH_ + KH_ + KH_
#define NHEADS 16
#define H_ 128
#define M_ (B_*T_)

typedef __nv_bfloat16 bf16;

#if defined(__CUDA_ARCH_FEAT_SM103_ALL) || defined(__CUDA_ARCH_FEAT_SM100_ALL)
#define HAS_TCGEN05 1
#else
#define HAS_TCGEN05 0
#endif

// ---------------------------------------------------------------------------
// Device-global scratch
// ---------------------------------------------------------------------------
__device__ float g_qkv[(size_t)M_ * QKV_];

__device__ bf16 g_x_hi[(size_t)M_ * C_],  g_x_lo[(size_t)M_ * C_];
__device__ bf16 g_e_hi[(size_t)M_ * NH_], g_e_lo[(size_t)M_ * NH_];
__device__ bf16 g_qh[(size_t)M_ * NH_],   g_ql[(size_t)M_ * NH_];
__device__ bf16 g_kh[(size_t)M_ * KH_],   g_kl[(size_t)M_ * KH_];
__device__ bf16 g_vth[(size_t)16 * 128 * T_], g_vtl[(size_t)16 * 128 * T_];
__device__ bf16 g_Wc_hi[(size_t)QKV_ * C_], g_Wc_lo[(size_t)QKV_ * C_];
__device__ bf16 g_Wo_hi[(size_t)C_ * NH_],  g_Wo_lo[(size_t)C_ * NH_];

// ---------------------------------------------------------------------------
// PTX helpers
// ---------------------------------------------------------------------------
__device__ __forceinline__ void cp16(void* dst, const void* src) {
    uint32_t d = (uint32_t)__cvta_generic_to_shared(dst);
    asm volatile("cp.async.cg.shared.global [%0], [%1], 16;\n" :: "r"(d), "l"(src));
}
__device__ __forceinline__ void mma16816(float* d, const uint32_t* a, const uint32_t* b) {
    asm volatile(
        "mma.sync.aligned.m16n8k16.row.col.f32.bf16.bf16.f32 "
        "{%0,%1,%2,%3},{%4,%5,%6,%7},{%8,%9},{%0,%1,%2,%3};\n"
        : "+f"(d[0]), "+f"(d[1]), "+f"(d[2]), "+f"(d[3])
        : "r"(a[0]), "r"(a[1]), "r"(a[2]), "r"(a[3]), "r"(b[0]), "r"(b[1]));
}

#if HAS_TCGEN05
#define MBAR_INIT(addr, cnt) \
    asm volatile("mbarrier.init.shared.b64 [%0], %1;" :: "r"(addr), "r"(cnt) : "memory")
#define MBAR_EXPECT_TX(addr, bytes) \
    asm volatile("mbarrier.arrive.expect_tx.shared.b64 _, [%0], %1;" \
                 :: "r"(addr), "r"(bytes) : "memory")
#define MBAR_WAIT(addr, parity) do {                                        \
    asm volatile(                                                            \
        "{\n\t.reg .pred P1;\n\t"                                            \
        "WAIT_LOOP_%=:\n\t"                                                  \
        "mbarrier.try_wait.parity.acquire.cta.shared::cta.b64 P1, [%0], %1, 0x989680;\n\t" \
        "@P1 bra.uni WAIT_DONE_%=;\n\t"                                      \
        "bra.uni WAIT_LOOP_%=;\n\t"                                          \
        "WAIT_DONE_%=:\n\t}"                                                 \
        :: "r"(addr), "r"(parity) : "memory");                               \
} while (0)
#define TC_ALLOC(smem_addr, n) \
    asm volatile("tcgen05.alloc.cta_group::1.sync.aligned.shared::cta.b32 [%0], %1;" \
                 :: "r"(smem_addr), "r"(n) : "memory")
#define TC_DEALLOC(tmem, n) \
    asm volatile("tcgen05.dealloc.cta_group::1.sync.aligned.b32 %0, %1;" :: "r"(tmem), "r"(n))
#define TC_RELINQ() \
    asm volatile("tcgen05.relinquish_alloc_permit.cta_group::1.sync.aligned;")
#define TC_COMMIT(mbar) \
    asm volatile("tcgen05.commit.cta_group::1.mbarrier::arrive::one.shared::cluster.b64 [%0];" \
                 :: "r"(mbar) : "memory")
#define TC_FENCE_AFTER()  asm volatile("tcgen05.fence::after_thread_sync;" ::: "memory")
#define TC_FENCE_BEFORE() asm volatile("tcgen05.fence::before_thread_sync;" ::: "memory")
#define TC_WAIT_LD() asm volatile("tcgen05.wait::ld.sync.aligned;" ::: "memory")
#define TC_WAIT_ST() asm volatile("tcgen05.wait::st.sync.aligned;" ::: "memory")

#define TC_LD_X32(r, addr) \
    asm volatile( \
        "tcgen05.ld.sync.aligned.32x32b.x32.b32 " \
        "{%0, %1, %2, %3, %4, %5, %6, %7, %8, %9, %10, %11, %12, %13, %14, %15, " \
        " %16, %17, %18, %19, %20, %21, %22, %23, %24, %25, %26, %27, %28, %29, %30, %31}, [%32];" \
        : "=r"((r)[0]),  "=r"((r)[1]),  "=r"((r)[2]),  "=r"((r)[3]), \
          "=r"((r)[4]),  "=r"((r)[5]),  "=r"((r)[6]),  "=r"((r)[7]), \
          "=r"((r)[8]),  "=r"((r)[9]),  "=r"((r)[10]), "=r"((r)[11]), \
          "=r"((r)[12]), "=r"((r)[13]), "=r"((r)[14]), "=r"((r)[15]), \
          "=r"((r)[16]), "=r"((r)[17]), "=r"((r)[18]), "=r"((r)[19]), \
          "=r"((r)[20]), "=r"((r)[21]), "=r"((r)[22]), "=r"((r)[23]), \
          "=r"((r)[24]), "=r"((r)[25]), "=r"((r)[26]), "=r"((r)[27]), \
          "=r"((r)[28]), "=r"((r)[29]), "=r"((r)[30]), "=r"((r)[31]) \
        : "r"(addr))

#define TC_ST_X32(addr, r) \
    asm volatile( \
        "tcgen05.st.sync.aligned.32x32b.x32.b32 [%0], " \
        "{%1, %2, %3, %4, %5, %6, %7, %8, %9, %10, %11, %12, %13, %14, %15, %16, " \
        " %17, %18, %19, %20, %21, %22, %23, %24, %25, %26, %27, %28, %29, %30, %31, %32};" \
        :: "r"(addr), \
           "r"((r)[0]),  "r"((r)[1]),  "r"((r)[2]),  "r"((r)[3]), \
           "r"((r)[4]),  "r"((r)[5]),  "r"((r)[6]),  "r"((r)[7]), \
           "r"((r)[8]),  "r"((r)[9]),  "r"((r)[10]), "r"((r)[11]), \
           "r"((r)[12]), "r"((r)[13]), "r"((r)[14]), "r"((r)[15]), \
           "r"((r)[16]), "r"((r)[17]), "r"((r)[18]), "r"((r)[19]), \
           "r"((r)[20]), "r"((r)[21]), "r"((r)[22]), "r"((r)[23]), \
           "r"((r)[24]), "r"((r)[25]), "r"((r)[26]), "r"((r)[27]), \
           "r"((r)[28]), "r"((r)[29]), "r"((r)[30]), "r"((r)[31]) \
        : "memory")

#define TC_ST_X16(addr, r) \
    asm volatile( \
        "tcgen05.st.sync.aligned.32x32b.x16.b32 [%0], " \
        "{%1, %2, %3, %4, %5, %6, %7, %8, %9, %10, %11, %12, %13, %14, %15, %16};" \
        :: "r"(addr), \
           "r"((r)[0]),  "r"((r)[1]),  "r"((r)[2]),  "r"((r)[3]), \
           "r"((r)[4]),  "r"((r)[5]),  "r"((r)[6]),  "r"((r)[7]), \
           "r"((r)[8]),  "r"((r)[9]),  "r"((r)[10]), "r"((r)[11]), \
           "r"((r)[12]), "r"((r)[13]), "r"((r)[14]), "r"((r)[15]) \
        : "memory")

__device__ __forceinline__ void tc_mma_ss_f16(
    uint32_t d_tmem, uint64_t a_desc, uint64_t b_desc, uint32_t idesc, uint32_t en)
{
    asm volatile(
        "{\n\t.reg .pred p;\n\t"
        "setp.ne.u32 p, %4, 0;\n\t"
        "tcgen05.mma.cta_group::1.kind::f16 [%0], %1, %2, %3, {%5, %5, %5, %5}, p;\n\t"
        "}"
        :: "r"(d_tmem), "l"(a_desc), "l"(b_desc), "r"(idesc), "r"(en), "r"(0u)
        : "memory");
}
__device__ __forceinline__ void tc_mma_ts_f16(
    uint32_t d_tmem, uint32_t a_tmem, uint64_t b_desc, uint32_t idesc, uint32_t en)
{
    asm volatile(
        "{\n\t.reg .pred p;\n\t"
        "setp.ne.u32 p, %4, 0;\n\t"
        "tcgen05.mma.cta_group::1.kind::f16 [%0], [%1], %2, %3, {%5, %5, %5, %5}, p;\n\t"
        "}"
        :: "r"(d_tmem), "r"(a_tmem), "l"(b_desc), "r"(idesc), "r"(en), "r"(0u)
        : "memory");
}
__device__ __forceinline__ uint64_t make_desc_sw128(uint32_t smem_addr) {
    return ((uint64_t)2 << 61) | ((uint64_t)1 << 46) | ((uint64_t)64 << 32)
         | ((uint64_t)1 << 16) | ((uint64_t)(smem_addr >> 4) & 0x3FFF);
}
__device__ __forceinline__ void tma2d(uint32_t smem_addr, const CUtensorMap* tmap,
                                      int ck, int crow, uint32_t mbar)
{
    asm volatile(
        "cp.async.bulk.tensor.2d.shared::cta.global.tile.mbarrier::complete_tx::bytes "
        "[%0], [%1, {%2, %3}], [%4];"
        :: "r"(smem_addr), "l"(tmap), "r"(ck), "r"(crow), "r"(mbar) : "memory");
}
#endif

// ---------------------------------------------------------------------------
// Dual-path GEMM: TMA + tcgen05 cg1, 128x256x64, 2 stages.
// R17: warp-specialized issuers — tid 32 = loader (done-wait gated, kt+2
// prefetch), tid 0 = MMA issuer (full-wait gated). MMA(kt+1) queues behind
// MMA(kt); done-waits no longer block MMA issue.
// ---------------------------------------------------------------------------
#define GBM 128
#define GBN 256
#define TBK 64
#define ST_A 16384
#define ST_B 32768
#define TSTAGE (2 * ST_A + 2 * ST_B)   // 98304
#define FBK 32
#define FLDA 40
#define FSSZ (128 * FLDA)
#define GEMM_SMEM (1024 + 2 * TSTAGE)
#define GEMM_IDESC 0x8400490u

__global__ __launch_bounds__(256) void gemm_dual(
    const bf16* __restrict__ Ah, const bf16* __restrict__ Al,
    const bf16* __restrict__ Bh, const bf16* __restrict__ Bl,
    const __grid_constant__ CUtensorMap tmAh,
    const __grid_constant__ CUtensorMap tmAl,
    const __grid_constant__ CUtensorMap tmBh,
    const __grid_constant__ CUtensorMap tmBl,
    float* __restrict__ Cc, int M, int N, int K)
{
#if HAS_TCGEN05
    extern __shared__ __align__(1024) char smem[];
    uint32_t sbase = (uint32_t)__cvta_generic_to_shared(smem);
    int tid = threadIdx.x, warp = tid >> 5, lane = tid & 31;
    int bx = blockIdx.x, by = blockIdx.y;
    const int ktiles = K / TBK;

    if (tid == 0) {
        MBAR_INIT(sbase + 16, 1);   // full[0]
        MBAR_INIT(sbase + 24, 1);   // full[1]
        MBAR_INIT(sbase + 32, 1);   // done[0]
        MBAR_INIT(sbase + 40, 1);   // done[1]
    }
    if (warp == 0) TC_ALLOC(sbase, 256);
    __syncthreads();
    uint32_t tmem;
    asm volatile("ld.shared.b32 %0, [%1];" : "=r"(tmem) : "r"(sbase));

    auto issue_load = [&](int kt) {
        if (kt < ktiles) {
            int s = kt & 1;
            uint32_t st = sbase + 1024 + (uint32_t)s * TSTAGE;
            uint32_t mb = sbase + 16 + (uint32_t)s * 8;
            MBAR_EXPECT_TX(mb, (uint32_t)TSTAGE);
            int k0 = kt * TBK;
            tma2d(st,                  &tmAh, k0, by * GBM, mb);
            tma2d(st + ST_A,           &tmAl, k0, by * GBM, mb);
            tma2d(st + 2 * ST_A,       &tmBh, k0, bx * GBN, mb);
            tma2d(st + 2 * ST_A + ST_B,&tmBl, k0, bx * GBN, mb);
        }
    };

    auto issue_mma = [&](int kt) {
        uint32_t a0 = sbase + 1024 + (uint32_t)(kt & 1) * TSTAGE;
        uint64_t dAh = make_desc_sw128(a0);
        uint64_t dAl = make_desc_sw128(a0 + ST_A);
        uint64_t dBh = make_desc_sw128(a0 + 2 * ST_A);
        uint64_t dBl = make_desc_sw128(a0 + 2 * ST_A + ST_B);
        #pragma unroll
        for (int ks = 0; ks < 4; ks++) {
            tc_mma_ss_f16(tmem, dAh + ks * 2, dBh + ks * 2, GEMM_IDESC,
                          (kt > 0 || ks > 0) ? 1u : 0u);
            tc_mma_ss_f16(tmem, dAh + ks * 2, dBl + ks * 2, GEMM_IDESC, 1u);
            tc_mma_ss_f16(tmem, dAl + ks * 2, dBh + ks * 2, GEMM_IDESC, 1u);
        }
        TC_COMMIT(sbase + 32 + (uint32_t)(kt & 1) * 8);
    };

    if (tid == 32) {
        // loader: prefetch two stages, then refill stage s as soon as
        // MMA(kt) (which read stage s) completes. Tracks every done phase,
        // so after the loop ALL MMAs are known complete.
        issue_load(0);
        issue_load(1);
        for (int kt = 0; kt < ktiles; kt++) {
            MBAR_WAIT(sbase + 32 + (uint32_t)(kt & 1) * 8,
                      (uint32_t)((kt >> 1) & 1));
            issue_load(kt + 2);
        }
    } else if (tid == 0) {
        // MMA issuer: gated only on data-ready; HW queue serializes MMAs.
        for (int kt = 0; kt < ktiles; kt++) {
            MBAR_WAIT(sbase + 16 + (uint32_t)(kt & 1) * 8,
                      (uint32_t)((kt >> 1) & 1));
            issue_mma(kt);
        }
    }
    __syncthreads();     // loader's final done-wait => all MMAs complete
    TC_FENCE_AFTER();

    int sp = warp & 3, chf = warp >> 2;
    #pragma unroll
    for (int cc = 0; cc < 4; cc++) {
        uint32_t dr[32];
        TC_LD_X32(dr, tmem + chf * 128 + cc * 32);
        TC_WAIT_LD();
        int row = by * GBM + sp * 32 + lane;
        int col = bx * GBN + chf * 128 + cc * 32;
        float* o = Cc + (size_t)row * N + col;
        #pragma unroll
        for (int q = 0; q < 8; q++)
            *(float4*)(o + q * 4) = make_float4(
                __uint_as_float(dr[4 * q]),     __uint_as_float(dr[4 * q + 1]),
                __uint_as_float(dr[4 * q + 2]), __uint_as_float(dr[4 * q + 3]));
    }
    __syncthreads();
    if (warp == 0) {
        TC_RELINQ();
        TC_DEALLOC(tmem, 256);
    }
#else
    // mma.sync fallback (PTX-only pass; runtime uses sm_103a cubin).
    extern __shared__ bf16 sm[];
    int tid = threadIdx.x;
    int by = blockIdx.y;
    int warp = tid >> 5, lane = tid & 31;
    int wm = (warp >> 2) * 64, wn = (warp & 3) * 32;
    int r = lane >> 2, c = lane & 3;

    for (int half = 0; half < 2; half++) {
        int bxe = blockIdx.x * 2 + half;
        const bf16* gAh = Ah + (size_t)(by * GBM) * K;
        const bf16* gAl = Al + (size_t)(by * GBM) * K;
        const bf16* gBh = Bh + (size_t)(bxe * 128) * K;
        const bf16* gBl = Bl + (size_t)(bxe * 128) * K;

        float acc[4][4][4];
        #pragma unroll
        for (int i = 0; i < 4; i++)
            #pragma unroll
            for (int j = 0; j < 4; j++)
                #pragma unroll
                for (int e = 0; e < 4; e++) acc[i][j][e] = 0.f;

        const int k_tiles = K / FBK;

        auto issue = [&](int stage, int kt) {
            if (kt < k_tiles) {
                size_t k0 = (size_t)kt * FBK;
                bf16* base = sm + stage * 4 * FSSZ;
                #pragma unroll
                for (int p = 0; p < 2; p++) {
                    int ci = tid + p * 256;
                    int row = ci >> 2, c16 = ci & 3;
                    int so = row * FLDA + c16 * 8;
                    size_t go = (size_t)row * K + k0 + c16 * 8;
                    cp16(base + so,            gAh + go);
                    cp16(base + FSSZ + so,     gAl + go);
                    cp16(base + 2 * FSSZ + so, gBh + go);
                    cp16(base + 3 * FSSZ + so, gBl + go);
                }
            }
            asm volatile("cp.async.commit_group;\n" ::);
        };

        #pragma unroll
        for (int s = 0; s < 2; s++) issue(s, s);

        for (int kt = 0; kt < k_tiles; kt++) {
            asm volatile("cp.async.wait_group 1;\n" ::);
            __syncthreads();
            issue((kt + 2) % 3, kt + 2);

            const uint32_t* wAh = (const uint32_t*)(sm + (kt % 3) * 4 * FSSZ);
            const uint32_t* wAl = wAh + FSSZ / 2;
            const uint32_t* wBh = wAh + FSSZ;
            const uint32_t* wBl = wAh + 3 * (FSSZ / 2);

            #pragma unroll
            for (int ks = 0; ks < 2; ks++) {
                int kw = ks * 8;
                uint32_t a_h[4][4], a_l[4][4], b_h[4][2], b_l[4][2];
                #pragma unroll
                for (int i = 0; i < 4; i++) {
                    int r0 = (wm + i * 16 + r) * 20 + kw + c;
                    int r1 = r0 + 8 * 20;
                    a_h[i][0] = wAh[r0];     a_h[i][1] = wAh[r1];
                    a_h[i][2] = wAh[r0 + 4]; a_h[i][3] = wAh[r1 + 4];
                    a_l[i][0] = wAl[r0];     a_l[i][1] = wAl[r1];
                    a_l[i][2] = wAl[r0 + 4]; a_l[i][3] = wAl[r1 + 4];
                }
                #pragma unroll
                for (int j = 0; j < 4; j++) {
                    int n0 = (wn + j * 8 + r) * 20 + kw + c;
                    b_h[j][0] = wBh[n0]; b_h[j][1] = wBh[n0 + 4];
                    b_l[j][0] = wBl[n0]; b_l[j][1] = wBl[n0 + 4];
                }
                #pragma unroll
                for (int i = 0; i < 4; i++)
                    #pragma unroll
                    for (int j = 0; j < 4; j++) {
                        mma16816(acc[i][j], a_h[i], b_h[j]);
                        mma16816(acc[i][j], a_h[i], b_l[j]);
                        mma16816(acc[i][j], a_l[i], b_h[j]);
                    }
            }
            __syncthreads();
        }

        #pragma unroll
        for (int i = 0; i < 4; i++)
            #pragma unroll
            for (int j = 0; j < 4; j++) {
                int row = by * GBM + wm + i * 16 + r;
                int col = bxe * 128 + wn + j * 8 + 2 * c;
                *(float2*)(Cc + (size_t)row * N + col) =
                    make_float2(acc[i][j][0], acc[i][j][1]);
                *(float2*)(Cc + (size_t)(row + 8) * N + col) =
                    make_float2(acc[i][j][2], acc[i][j][3]);
            }
        __syncthreads();
    }
#endif
}

// ---------------------------------------------------------------------------
// tcgen05 flash attention — exact R12 version (passing at 990us)
// TMEM: O@0(128), Qh@128(64), Ql@192(64), S0@256, S1@320, Ph@384(32), Pl@416(32)
// ---------------------------------------------------------------------------
#define AK_B 16384
#define ASTAGE (4 * AK_B)
#define ATTN_TC_SMEM (1024 + 3 * ASTAGE)
#define IDESC_S  0x8100490u
#define IDESC_PV 0x8200490u

__global__ __launch_bounds__(256) void attn_tc(
    const bf16* __restrict__ qh, const bf16* __restrict__ ql,
    const bf16* __restrict__ kh_, const bf16* __restrict__ kl_,
    const bf16* __restrict__ vth, const bf16* __restrict__ vtl,
    bf16* __restrict__ eh, bf16* __restrict__ el)
{
#if HAS_TCGEN05
    extern __shared__ __align__(1024) char smem[];
    __shared__ float sL[2][128];
    uint32_t sbase = (uint32_t)__cvta_generic_to_shared(smem);
    int tid = threadIdx.x, warp = tid >> 5, lane = tid & 31;
    int b = blockIdx.z, n = blockIdx.y, khd = n >> 2;
    int q0 = blockIdx.x * 128, bT = b * T_;
    const int NT = T_ / 64;

    if (tid == 0) {
        MBAR_INIT(sbase + 8, 1);
        MBAR_INIT(sbase + 16, 1);
        MBAR_INIT(sbase + 24, 1);
    }
    if (warp == 0) TC_ALLOC(sbase, 512);
    __syncthreads();
    uint32_t tmem;
    asm volatile("ld.shared.b32 %0, [%1];" : "=r"(tmem) : "r"(sbase));

    auto issue_k = [&](int tile) {
        if (tile < NT) {
            int s0 = tile * 64;
            char* st = smem + 1024 + (tile % 3) * ASTAGE;
            #pragma unroll
            for (int a = 0; a < 2; a++) {
                const bf16* g = (a ? kl_ : kh_);
                char* base = st + a * AK_B;
                #pragma unroll
                for (int it = 0; it < 4; it++) {
                    int idx = tid + it * 256;
                    int s = idx >> 4, ch = idx & 15;
                    uint32_t off = (uint32_t)((s >> 3) * 1024 + (ch >> 3) * 8192
                                            + (s & 7) * 128 + (ch & 7) * 16);
                    off ^= ((off >> 3) & 0x70);
                    cp16(base + off, g + (size_t)(bT + s0 + s) * KH_ + khd * 128 + ch * 8);
                }
            }
        }
        asm volatile("cp.async.commit_group;\n" ::);
    };
    auto issue_v = [&](int tile) {
        if (tile < NT) {
            int s0 = tile * 64;
            char* st = smem + 1024 + (tile % 3) * ASTAGE;
            #pragma unroll
            for (int a = 0; a < 2; a++) {
                const bf16* g = (a ? vtl : vth);
                char* base = st + 2 * AK_B + a * AK_B;
                #pragma unroll
                for (int it = 0; it < 4; it++) {
                    int idx = tid + it * 256;
                    int h = idx >> 3, tch = idx & 7;
                    uint32_t off = (uint32_t)((h >> 3) * 1024 + (h & 7) * 128 + tch * 16);
                    off ^= ((off >> 3) & 0x70);
                    cp16(base + off,
                         g + ((size_t)(b * 4 + khd) * 128 + h) * T_ + s0 + tch * 8);
                }
            }
        }
        asm volatile("cp.async.commit_group;\n" ::);
    };

    auto issue_S = [&](int tile) {
        uint32_t kb = sbase + 1024 + (uint32_t)(tile % 3) * ASTAGE;
        uint64_t dKh = make_desc_sw128(kb);
        uint64_t dKl = make_desc_sw128(kb + AK_B);
        uint32_t sdst = tmem + 256 + (uint32_t)(tile & 1) * 64;
        #pragma unroll
        for (int ks = 0; ks < 8; ks++) {
            uint64_t koff = (ks < 4) ? (uint64_t)(ks * 2)
                                     : (uint64_t)(512 + (ks - 4) * 2);
            uint32_t aH = tmem + 128 + ks * 8, aL = tmem + 192 + ks * 8;
            tc_mma_ts_f16(sdst, aH, dKh + koff, IDESC_S, ks > 0 ? 1u : 0u);
            tc_mma_ts_f16(sdst, aH, dKl + koff, IDESC_S, 1u);
            tc_mma_ts_f16(sdst, aL, dKh + koff, IDESC_S, 1u);
        }
        TC_COMMIT(sbase + 8 + (uint32_t)(tile & 1) * 8);
    };

    issue_k(0);
    issue_v(0);
    issue_k(1);
    issue_v(1);

    if (tid < 128) {
        uint32_t woffq = (uint32_t)(tid >> 5) << 21;
        uint32_t qr[32];
        const uint4* srcA = (const uint4*)(qh + (size_t)(bT + q0 + tid) * NH_ + n * 128);
        const uint4* srcB = (const uint4*)(ql + (size_t)(bT + q0 + tid) * NH_ + n * 128);
        #pragma unroll
        for (int i = 0; i < 8; i++) {
            uint4 v = srcA[i];
            qr[4*i] = v.x; qr[4*i+1] = v.y; qr[4*i+2] = v.z; qr[4*i+3] = v.w;
        }
        TC_ST_X32(tmem + 128 + woffq, qr);
        #pragma unroll
        for (int i = 0; i < 8; i++) {
            uint4 v = srcA[i + 8];
            qr[4*i] = v.x; qr[4*i+1] = v.y; qr[4*i+2] = v.z; qr[4*i+3] = v.w;
        }
        TC_ST_X32(tmem + 160 + woffq, qr);
        #pragma unroll
        for (int i = 0; i < 8; i++) {
            uint4 v = srcB[i];
            qr[4*i] = v.x; qr[4*i+1] = v.y; qr[4*i+2] = v.z; qr[4*i+3] = v.w;
        }
        TC_ST_X32(tmem + 192 + woffq, qr);
        #pragma unroll
        for (int i = 0; i < 8; i++) {
            uint4 v = srcB[i + 8];
            qr[4*i] = v.x; qr[4*i+1] = v.y; qr[4*i+2] = v.z; qr[4*i+3] = v.w;
        }
        TC_ST_X32(tmem + 224 + woffq, qr);
        TC_WAIT_ST();
    }
    TC_FENCE_BEFORE();
    asm volatile("cp.async.wait_group 2;\n" ::);
    __syncthreads();

    if (tid == 0) {
        TC_FENCE_AFTER();
        asm volatile("fence.proxy.async.shared::cta;" ::: "memory");
        issue_S(0);
    }

    int chalf = warp >> 2;
    int row = (warp & 3) * 32 + lane;
    uint32_t woff = (uint32_t)(warp & 3) << 21;
    float li = 0.f;

    for (int t = 0; t < NT; t++) {
        MBAR_WAIT(sbase + 8 + (uint32_t)(t & 1) * 8, (uint32_t)((t >> 1) & 1));
        TC_FENCE_AFTER();
        issue_k(t + 2);

        asm volatile("cp.async.wait_group 1;\n" ::);
        __syncthreads();
        if (tid == 0 && t + 1 < NT) {
            asm volatile("fence.proxy.async.shared::cta;" ::: "memory");
            issue_S(t + 1);
        }

        uint32_t sr[32];
        TC_LD_X32(sr, tmem + 256 + (uint32_t)(t & 1) * 64 + chalf * 32);
        TC_WAIT_LD();
        float pv[32];
        float lsum = 0.f;
        #pragma unroll
        for (int i = 0; i < 32; i++) {
            pv[i] = __expf(__uint_as_float(sr[i]));
            lsum += pv[i];
        }
        li += lsum;
        uint32_t ph[16], pl[16];
        #pragma unroll
        for (int j = 0; j < 16; j++) {
            float p0 = pv[2*j], p1 = pv[2*j+1];
            bf16 h0 = __float2bfloat16(p0), h1 = __float2bfloat16(p1);
            __nv_bfloat162 hp = {h0, h1};
            __nv_bfloat162 lp = {__float2bfloat16(p0 - __bfloat162float(h0)),
                                 __float2bfloat16(p1 - __bfloat162float(h1))};
            ph[j] = *(uint32_t*)&hp;
            pl[j] = *(uint32_t*)&lp;
        }

        if (t >= 1) MBAR_WAIT(sbase + 24, (uint32_t)((t - 1) & 1));
        TC_FENCE_AFTER();

        issue_v(t + 2);

        TC_ST_X16(tmem + 384 + chalf * 16 + woff, ph);
        TC_ST_X16(tmem + 416 + chalf * 16 + woff, pl);
        TC_WAIT_ST();
        TC_FENCE_BEFORE();
        __syncthreads();

        if (tid == 0) {
            TC_FENCE_AFTER();
            asm volatile("fence.proxy.async.shared::cta;" ::: "memory");
            uint32_t vb = sbase + 1024 + (uint32_t)(t % 3) * ASTAGE + 2 * AK_B;
            uint64_t dVh = make_desc_sw128(vb);
            uint64_t dVl = make_desc_sw128(vb + AK_B);
            #pragma unroll
            for (int ks = 0; ks < 4; ks++) {
                uint32_t aH = tmem + 384 + ks * 8, aL = tmem + 416 + ks * 8;
                tc_mma_ts_f16(tmem, aH, dVh + ks * 2, IDESC_PV,
                              (t > 0 || ks > 0) ? 1u : 0u);
                tc_mma_ts_f16(tmem, aH, dVl + ks * 2, IDESC_PV, 1u);
                tc_mma_ts_f16(tmem, aL, dVh + ks * 2, IDESC_PV, 1u);
            }
            TC_COMMIT(sbase + 24);
        }
    }

    sL[chalf][row] = li;
    __syncthreads();
    float inv = 1.f / (sL[0][row] + sL[1][row]);

    MBAR_WAIT(sbase + 24, (uint32_t)((NT - 1) & 1));
    TC_FENCE_AFTER();

    uint32_t o0[32], o1[32];
    TC_LD_X32(o0, tmem + chalf * 64);
    TC_LD_X32(o1, tmem + chalf * 64 + 32);
    TC_WAIT_LD();

    size_t obase = (size_t)(bT + q0 + row) * NH_ + n * 128 + chalf * 64;
    #pragma unroll
    for (int j = 0; j < 16; j++) {
        float v0 = __uint_as_float(j < 8 ? o0[4*(j&7)]   : o1[4*(j&7)])   * inv;
        float v1 = __uint_as_float(j < 8 ? o0[4*(j&7)+1] : o1[4*(j&7)+1]) * inv;
        float v2 = __uint_as_float(j < 8 ? o0[4*(j&7)+2] : o1[4*(j&7)+2]) * inv;
        float v3 = __uint_as_float(j < 8 ? o0[4*(j&7)+3] : o1[4*(j&7)+3]) * inv;
        bf16 h0 = __float2bfloat16(v0), h1 = __float2bfloat16(v1);
        bf16 h2 = __float2bfloat16(v2), h3 = __float2bfloat16(v3);
        __nv_bfloat162 hp0 = {h0, h1}, hp1 = {h2, h3};
        __nv_bfloat162 lp0 = {__float2bfloat16(v0 - __bfloat162float(h0)),
                              __float2bfloat16(v1 - __bfloat162float(h1))};
        __nv_bfloat162 lp1 = {__float2bfloat16(v2 - __bfloat162float(h2)),
                              __float2bfloat16(v3 - __bfloat162float(h3))};
        int colo = (j & 7) * 4 + (j < 8 ? 0 : 32);
        *(uint2*)(eh + obase + colo) = make_uint2(*(uint32_t*)&hp0, *(uint32_t*)&hp1);
        *(uint2*)(el + obase + colo) = make_uint2(*(uint32_t*)&lp0, *(uint32_t*)&lp1);
    }

    __syncthreads();
    if (warp == 0) {
        TC_RELINQ();
        TC_DEALLOC(tmem, 512);
    }
#endif
}

// ---------------------------------------------------------------------------
// Prep kernels (unchanged)
// ---------------------------------------------------------------------------
__global__ __launch_bounds__(256) void split_f32(
    const float* __restrict__ src, bf16* __restrict__ hi, bf16* __restrict__ lo,
    size_t n4)
{
    size_t i = (size_t)blockIdx.x * blockDim.x + threadIdx.x;
    if (i >= n4) return;
    float4 v = *(const float4*)(src + i * 4);
    bf16 h0 = __float2bfloat16(v.x), h1 = __float2bfloat16(v.y);
    bf16 h2 = __float2bfloat16(v.z), h3 = __float2bfloat16(v.w);
    bf16 l0 = __float2bfloat16(v.x - __bfloat162float(h0));
    bf16 l1 = __float2bfloat16(v.y - __bfloat162float(h1));
    bf16 l2 = __float2bfloat16(v.z - __bfloat162float(h2));
    bf16 l3 = __float2bfloat16(v.w - __bfloat162float(h3));
    __nv_bfloat162 hp0 = {h0, h1}, hp1 = {h2, h3};
    __nv_bfloat162 lp0 = {l0, l1}, lp1 = {l2, l3};
    *(uint2*)(hi + i * 4) = make_uint2(*(unsigned int*)&hp0, *(unsigned int*)&hp1);
    *(uint2*)(lo + i * 4) = make_uint2(*(unsigned int*)&lp0, *(unsigned int*)&lp1);
}

__global__ __launch_bounds__(256) void tsplit_wc(
    const float* __restrict__ Wq, const float* __restrict__ Wk,
    const float* __restrict__ Wv, bf16* __restrict__ hi, bf16* __restrict__ lo)
{
    __shared__ float t[32][33];
    int kb = blockIdx.y * 32;
    int nb = blockIdx.x * 32;
    const float* W;
    int srcN, srcCol;
    if (nb < NH_)            { W = Wq; srcN = NH_; srcCol = nb; }
    else if (nb < NH_ + KH_) { W = Wk; srcN = KH_; srcCol = nb - NH_; }
    else                     { W = Wv; srcN = KH_; srcCol = nb - NH_ - KH_; }
    #pragma unroll
    for (int i = 0; i < 4; i++)
        t[threadIdx.y + 8 * i][threadIdx.x] =
            W[(size_t)(kb + threadIdx.y + 8 * i) * srcN + srcCol + threadIdx.x];
    __syncthreads();
    #pragma unroll
    for (int i = 0; i < 4; i++) {
        float f = t[threadIdx.x][threadIdx.y + 8 * i];
        bf16 h = __float2bfloat16(f);
        size_t idx = (size_t)(nb + threadIdx.y + 8 * i) * C_ + kb + threadIdx.x;
        hi[idx] = h;
        lo[idx] = __float2bfloat16(f - __bfloat162float(h));
    }
}

__global__ __launch_bounds__(256) void tsplit(
    const float* __restrict__ W, bf16* __restrict__ hi, bf16* __restrict__ lo,
    int K, int N)
{
    __shared__ float t[32][33];
    int kb = blockIdx.y * 32, nb = blockIdx.x * 32;
    #pragma unroll
    for (int i = 0; i < 4; i++)
        t[threadIdx.y + 8 * i][threadIdx.x] =
            W[(size_t)(kb + threadIdx.y + 8 * i) * N + nb + threadIdx.x];
    __syncthreads();
    #pragma unroll
    for (int i = 0; i < 4; i++) {
        float f = t[threadIdx.x][threadIdx.y + 8 * i];
        bf16 h = __float2bfloat16(f);
        size_t idx = (size_t)(nb + threadIdx.y + 8 * i) * K + kb + threadIdx.x;
        hi[idx] = h;
        lo[idx] = __float2bfloat16(f - __bfloat162float(h));
    }
}

__global__ __launch_bounds__(256) void vtsplit(
    const float* __restrict__ qkv, bf16* __restrict__ hi, bf16* __restrict__ lo)
{
    __shared__ float t[32][33];
    int t0 = blockIdx.x * 32, h0 = blockIdx.y * 32;
    int bz = blockIdx.z;
    int b = bz >> 2, kh = bz & 3;
    #pragma unroll
    for (int i = 0; i < 4; i++)
        t[threadIdx.y + 8 * i][threadIdx.x] =
            qkv[(size_t)(b * T_ + t0 + threadIdx.y + 8 * i) * QKV_ + 2560 + kh * 128 + h0 + threadIdx.x];
    __syncthreads();
    #pragma unroll
    for (int i = 0; i < 4; i++) {
        float f = t[threadIdx.x][threadIdx.y + 8 * i];
        bf16 h = __float2bfloat16(f);
        size_t idx = ((size_t)bz * 128 + h0 + threadIdx.y + 8 * i) * T_ + t0 + threadIdx.x;
        hi[idx] = h;
        lo[idx] = __float2bfloat16(f - __bfloat162float(h));
    }
}

__global__ __launch_bounds__(256) void rms_rope_split(
    const float* __restrict__ in, int inoff,
    bf16* __restrict__ outh, bf16* __restrict__ outl,
    int width, int nheads, float outscale)
{
    int row = blockIdx.x;
    int t = row % T_;
    const float* ptr = in + (size_t)row * QKV_ + inoff;

    float ss = 0.f;
    for (int i = threadIdx.x; i < width; i += 256) {
        float v = ptr[i];
        ss += v * v;
    }
    #pragma unroll
    for (int o = 16; o; o >>= 1) ss += __shfl_xor_sync(0xffffffffu, ss, o);
    __shared__ float red[8];
    if ((threadIdx.x & 31) == 0) red[threadIdx.x >> 5] = ss;
    __syncthreads();
    float tot = red[0] + red[1] + red[2] + red[3] + red[4] + red[5] + red[6] + red[7];
    float rs = rsqrtf(tot / (float)width + 1e-6f) * outscale;

    int npairs = nheads * 64;
    const double TWO_PI = 6.283185307179586476925286766559;
    bf16* oh = outh + (size_t)row * width;
    bf16* ol = outl + (size_t)row * width;
    for (int p = threadIdx.x; p < npairs; p += 256) {
        int head = p >> 6;
        int hp = p & 63;
        float inv = __expf(-(float)hp * (9.210340371976184f / 64.f));
        float theta = (float)t * inv;
        double td = (double)theta * (1.0 / TWO_PI);
        double frac = td - floor(td);
        if (frac > 0.5) frac -= 1.0;
        float redang = (float)(frac * TWO_PI);
        float s, cc;
        sincosf(redang, &s, &cc);

        int base = head * H_;
        float x1 = ptr[base + hp] * rs;
        float x2 = ptr[base + hp + 64] * rs;
        float y1 = x1 * cc - x2 * s;
        float y2 = x2 * cc + x1 * s;
        bf16 h1 = __float2bfloat16(y1), h2 = __float2bfloat16(y2);
        oh[base + hp]      = h1;
        oh[base + hp + 64] = h2;
        ol[base + hp]      = __float2bfloat16(y1 - __bfloat162float(h1));
        ol[base + hp + 64] = __float2bfloat16(y2 - __bfloat162float(h2));
    }
}

// ---------------------------------------------------------------------------
// Host: tensormap encode via runtime-resolved driver entry point
// ---------------------------------------------------------------------------
typedef CUresult (*PFN_tmapEncode)(
    CUtensorMap*, CUtensorMapDataType, unsigned int, void*,
    const unsigned long long*, const unsigned long long*,
    const unsigned int*, const unsigned int*,
    CUtensorMapInterleave, CUtensorMapSwizzle,
    CUtensorMapL2promotion, CUtensorMapFloatOOBfill);

static void make_tmap(CUtensorMap* tm, void* ptr, int rows, int K, int boxRows)
{
    PFN_tmapEncode enc = nullptr;
    cudaDriverEntryPointQueryResult st;
    cudaGetDriverEntryPoint("cuTensorMapEncodeTiled", (void**)&enc,
                            cudaEnableDefault, &st);
    unsigned long long dims[2]    = {(unsigned long long)K, (unsigned long long)rows};
    unsigned long long strides[1] = {(unsigned long long)K * 2};
    unsigned int box[2] = {64u, (unsigned int)boxRows};
    unsigned int es[2]  = {1u, 1u};
    enc(tm, CU_TENSOR_MAP_DATA_TYPE_BFLOAT16, 2, ptr, dims, strides, box, es,
        CU_TENSOR_MAP_INTERLEAVE_NONE, CU_TENSOR_MAP_SWIZZLE_128B,
        CU_TENSOR_MAP_L2_PROMOTION_L2_128B, CU_TENSOR_MAP_FLOAT_OOB_FILL_NONE);
}

// ---------------------------------------------------------------------------
extern "C" void kernel_launch(void* const* d_in, const int* in_sizes, int n_in,
                              void* d_out, int out_size)
{
    const float* x    = (const float*)d_in[0];
    const float* Wq   = (const float*)d_in[1];
    const float* Wk   = (const float*)d_in[2];
    const float* Wv   = (const float*)d_in[3];
    const float* Wout = (const float*)d_in[4];
    float* out = (float*)d_out;

    float* qkv;
    cudaGetSymbolAddress((void**)&qkv, g_qkv);
    bf16 *xh, *xl, *eh, *el, *qsh, *qsl, *ksh, *ksl, *vth, *vtl;
    bf16 *wch, *wcl, *woh, *wol;
    cudaGetSymbolAddress((void**)&xh, g_x_hi);   cudaGetSymbolAddress((void**)&xl, g_x_lo);
    cudaGetSymbolAddress((void**)&eh, g_e_hi);   cudaGetSymbolAddress((void**)&el, g_e_lo);
    cudaGetSymbolAddress((void**)&qsh, g_qh);    cudaGetSymbolAddress((void**)&qsl, g_ql);
    cudaGetSymbolAddress((void**)&ksh, g_kh);    cudaGetSymbolAddress((void**)&ksl, g_kl);
    cudaGetSymbolAddress((void**)&vth, g_vth);   cudaGetSymbolAddress((void**)&vtl, g_vtl);
    cudaGetSymbolAddress((void**)&wch, g_Wc_hi); cudaGetSymbolAddress((void**)&wcl, g_Wc_lo);
    cudaGetSymbolAddress((void**)&woh, g_Wo_hi); cudaGetSymbolAddress((void**)&wol, g_Wo_lo);

    cudaFuncSetAttribute(gemm_dual, cudaFuncAttributeMaxDynamicSharedMemorySize,
                         GEMM_SMEM);
    cudaFuncSetAttribute(attn_tc, cudaFuncAttributeMaxDynamicSharedMemorySize,
                         ATTN_TC_SMEM);

    // tensormaps (host-side, by-value kernel params; graph-safe)
    CUtensorMap tmXh, tmXl, tmWch, tmWcl, tmEh, tmEl, tmWoh, tmWol;
    make_tmap(&tmXh,  xh,  M_,   C_,  128);
    make_tmap(&tmXl,  xl,  M_,   C_,  128);
    make_tmap(&tmWch, wch, QKV_, C_,  256);
    make_tmap(&tmWcl, wcl, QKV_, C_,  256);
    make_tmap(&tmEh,  eh,  M_,   NH_, 128);
    make_tmap(&tmEl,  el,  M_,   NH_, 128);
    make_tmap(&tmWoh, woh, C_,   NH_, 256);
    make_tmap(&tmWol, wol, C_,   NH_, 256);

    // prep
    split_f32<<<(int)((M_ * (size_t)C_ / 4 + 255) / 256), 256>>>(x, xh, xl, (size_t)M_ * C_ / 4);
    tsplit_wc<<<dim3(QKV_ / 32, C_ / 32), dim3(32, 8)>>>(Wq, Wk, Wv, wch, wcl);
    tsplit<<<dim3(C_ / 32, NH_ / 32), dim3(32, 8)>>>(Wout, woh, wol, NH_, C_);

    // launch 4: fused QKV projection (tcgen05 + TMA, warp-specialized) — profiled
    gemm_dual<<<dim3(QKV_ / GBN, M_ / GBM), 256, GEMM_SMEM>>>(
        xh, xl, wch, wcl, tmXh, tmXl, tmWch, tmWcl, qkv, M_, QKV_, C_);

    // norm + rope -> split bf16 ; V transpose+split
    rms_rope_split<<<M_, 256>>>(qkv, 0,    qsh, qsl, NH_, NHEADS, 0.08838834764831845f);
    rms_rope_split<<<M_, 256>>>(qkv, 2048, ksh, ksl, KH_, 4, 1.0f);
    vtsplit<<<dim3(T_ / 32, 4, 16), dim3(32, 8)>>>(qkv, vth, vtl);

    // attention (tcgen05, exact R12 pipeline)
    dim3 gAttn(T_ / 128, NHEADS, B_);
    attn_tc<<<gAttn, 256, ATTN_TC_SMEM>>>(qsh, qsl, ksh, ksl, vth, vtl, eh, el);

    // output projection (tcgen05 + TMA, warp-specialized)
    gemm_dual<<<dim3(C_ / GBN, M_ / GBM), 256, GEMM_SMEM>>>(
        eh, el, woh, wol, tmEh, tmEl, tmWoh, tmWol, out, M_, C_, NH_);
}